// round 5
// baseline (speedup 1.0000x reference)
#include <cuda_runtime.h>
#include <cuda_bf16.h>
#include <math.h>
#include <stdint.h>

#define V     49152
#define BATCH 2
#define M     (BATCH*V)      // 98304
#define DEG   20
#define CIN   128
#define CMID  64

// ---------------- scratch (device globals; zero-initialized) ------------------
__device__ __align__(128) float g_y1[M*CMID];
__device__ __align__(128) float g_t1[M*CMID];
__device__ __align__(128) float g_t2[M*CMID];
__device__ __align__(128) float g_y2[M*CMID];
__device__ __align__(128) float g_sum[3*128];
__device__ __align__(128) float g_sq [3*128];
__device__ __align__(128) float g_scale[3*128];
__device__ __align__(128) float g_shift[3*128];
__device__ unsigned int g_ctr[3];

// ---------------- mma.sync m16n8k16 bf16 (legacy HMMA; ok on compute_103) -----
__device__ __forceinline__ void mma16816(float* c, const uint32_t* a, const uint32_t* b) {
    asm volatile(
        "mma.sync.aligned.m16n8k16.row.col.f32.bf16.bf16.f32 "
        "{%0,%1,%2,%3}, {%4,%5,%6,%7}, {%8,%9}, {%0,%1,%2,%3};"
        : "+f"(c[0]), "+f"(c[1]), "+f"(c[2]), "+f"(c[3])
        : "r"(a[0]), "r"(a[1]), "r"(a[2]), "r"(a[3]), "r"(b[0]), "r"(b[1]));
}

__device__ __forceinline__ uint32_t pack2(__nv_bfloat16 a, __nv_bfloat16 b) {
    __nv_bfloat162 h; h.x = a; h.y = b;
    return *reinterpret_cast<uint32_t*>(&h);
}

// ---------------- tensor-core GEMM (HMMA) + fused BN-stats + finalize ----------
// Y[128-row tile, NOUT] = sum_s A_s[tile, K] @ W[s*K.., NOUT] + bias
// bf16 hi/lo split (hi*hi + hi*lo + lo*hi), fp32 accumulators.
// BN0: fused BN+ReLU on source 0 while staging A.
// Epilogue: per-channel sum/sumsq -> global atomics; last block computes
// scale/shift for THIS layer's BN and resets the accumulators (replay-safe).
template<int K, int NOUT, int NSRC, bool BN0>
__global__ void __launch_bounds__(256) gemm_mma(
    const float* __restrict__ A0, const float* __restrict__ A1, const float* __restrict__ A2,
    const float* __restrict__ W, const float* __restrict__ bias,
    const float* __restrict__ bsc, const float* __restrict__ bsh,
    float* __restrict__ Y,
    const float* __restrict__ gamma, const float* __restrict__ beta,
    float* __restrict__ gs, float* __restrict__ gq,
    float* __restrict__ oscale, float* __restrict__ oshift,
    unsigned int* __restrict__ ctr)
{
    constexpr int KT = NSRC*K;
    constexpr int SA = KT + 8;                  // padded stride -> conflict-free frags
    constexpr int ABYTES = 128*SA*2;
    constexpr int WBYTES = NOUT*SA*2;

    extern __shared__ char smc[];
    __nv_bfloat16* Ah = (__nv_bfloat16*)(smc);
    __nv_bfloat16* Al = (__nv_bfloat16*)(smc + ABYTES);
    __nv_bfloat16* Wh = (__nv_bfloat16*)(smc + 2*ABYTES);
    __nv_bfloat16* Wl = (__nv_bfloat16*)(smc + 2*ABYTES + WBYTES);

    const int t    = threadIdx.x;
    const int wid  = t >> 5, lane = t & 31;
    const int row0 = blockIdx.x * 128;
    const int g    = lane >> 2, tg = lane & 3;

    // ---- stage W transposed: Wt[n][kt] = W[kt][n], hi/lo ----
    for (int i = t; i < KT*NOUT; i += 256) {
        int n = i % NOUT, k = i / NOUT;
        float w = W[i];
        __nv_bfloat16 h = __float2bfloat16(w);
        Wh[n*SA + k] = h;
        Wl[n*SA + k] = __float2bfloat16(w - __bfloat162float(h));
    }

    // ---- stage A: [128][KT] hi/lo, optional fused BN+ReLU on source 0 ----
    #pragma unroll
    for (int s = 0; s < NSRC; ++s) {
        const float* A = (s == 0) ? A0 : ((s == 1) ? A1 : A2);
        for (int i = t; i < 128*(K/4); i += 256) {
            int r = i / (K/4), c4 = i % (K/4);
            float4 v = *(const float4*)(A + (size_t)(row0 + r)*K + c4*4);
            if (BN0 && s == 0) {
                float4 sc = *(const float4*)(bsc + c4*4);
                float4 sh = *(const float4*)(bsh + c4*4);
                v.x = fmaxf(fmaf(v.x, sc.x, sh.x), 0.f);
                v.y = fmaxf(fmaf(v.y, sc.y, sh.y), 0.f);
                v.z = fmaxf(fmaf(v.z, sc.z, sh.z), 0.f);
                v.w = fmaxf(fmaf(v.w, sc.w, sh.w), 0.f);
            }
            __nv_bfloat16 hx = __float2bfloat16(v.x), hy = __float2bfloat16(v.y);
            __nv_bfloat16 hz = __float2bfloat16(v.z), hw = __float2bfloat16(v.w);
            int col = s*K + c4*4;
            uint32_t* dh = (uint32_t*)(Ah + r*SA + col);
            uint32_t* dl = (uint32_t*)(Al + r*SA + col);
            dh[0] = pack2(hx, hy);
            dh[1] = pack2(hz, hw);
            dl[0] = pack2(__float2bfloat16(v.x - __bfloat162float(hx)),
                          __float2bfloat16(v.y - __bfloat162float(hy)));
            dl[1] = pack2(__float2bfloat16(v.z - __bfloat162float(hz)),
                          __float2bfloat16(v.w - __bfloat162float(hw)));
        }
    }
    __syncthreads();

    // ---- compute: warp owns rows [wid*16, wid*16+16), all NOUT cols ----
    constexpr int NB = NOUT/8;
    float acc[NB][4];
    #pragma unroll
    for (int nb = 0; nb < NB; ++nb)
        acc[nb][0] = acc[nb][1] = acc[nb][2] = acc[nb][3] = 0.f;

    const int rb = wid*16;
    const __nv_bfloat16* arow0 = Ah + (rb + g)*SA;
    const __nv_bfloat16* arow8 = Ah + (rb + g + 8)*SA;
    const __nv_bfloat16* lrow0 = Al + (rb + g)*SA;
    const __nv_bfloat16* lrow8 = Al + (rb + g + 8)*SA;

    #pragma unroll 2
    for (int kk = 0; kk < KT/16; ++kk) {
        const int kb = kk*16 + tg*2;
        uint32_t ah[4], al[4];
        ah[0] = *(const uint32_t*)(arow0 + kb);
        ah[1] = *(const uint32_t*)(arow8 + kb);
        ah[2] = *(const uint32_t*)(arow0 + kb + 8);
        ah[3] = *(const uint32_t*)(arow8 + kb + 8);
        al[0] = *(const uint32_t*)(lrow0 + kb);
        al[1] = *(const uint32_t*)(lrow8 + kb);
        al[2] = *(const uint32_t*)(lrow0 + kb + 8);
        al[3] = *(const uint32_t*)(lrow8 + kb + 8);
        #pragma unroll
        for (int nb = 0; nb < NB; ++nb) {
            const __nv_bfloat16* wrow = Wh + (nb*8 + g)*SA;
            const __nv_bfloat16* wlo  = Wl + (nb*8 + g)*SA;
            uint32_t bh[2], bl[2];
            bh[0] = *(const uint32_t*)(wrow + kb);
            bh[1] = *(const uint32_t*)(wrow + kb + 8);
            bl[0] = *(const uint32_t*)(wlo  + kb);
            bl[1] = *(const uint32_t*)(wlo  + kb + 8);
            mma16816(acc[nb], ah, bh);   // hi*hi
            mma16816(acc[nb], ah, bl);   // hi*lo
            mma16816(acc[nb], al, bh);   // lo*hi
        }
    }

    __syncthreads();   // compute done -> smem reusable for stats reduction
    float* redS = (float*)smc;               // [8][NOUT]
    float* redQ = (float*)smc + 8*NOUT;      // [8][NOUT]

    // ---- store + per-warp column partials ----
    {
        float* y0 = Y + (size_t)(row0 + rb + g)*NOUT;
        float* y8 = Y + (size_t)(row0 + rb + g + 8)*NOUT;
        #pragma unroll
        for (int nb = 0; nb < NB; ++nb) {
            int c = nb*8 + tg*2;
            float2 bb = __ldg((const float2*)(bias + c));
            float y00 = acc[nb][0] + bb.x, y01 = acc[nb][1] + bb.y;
            float y80 = acc[nb][2] + bb.x, y81 = acc[nb][3] + bb.y;
            *(float2*)(y0 + c) = make_float2(y00, y01);
            *(float2*)(y8 + c) = make_float2(y80, y81);
            float s0 = y00 + y80, q0 = y00*y00 + y80*y80;
            float s1 = y01 + y81, q1 = y01*y01 + y81*y81;
            #pragma unroll
            for (int off = 4; off <= 16; off <<= 1) {
                s0 += __shfl_xor_sync(0xffffffffu, s0, off);
                q0 += __shfl_xor_sync(0xffffffffu, q0, off);
                s1 += __shfl_xor_sync(0xffffffffu, s1, off);
                q1 += __shfl_xor_sync(0xffffffffu, q1, off);
            }
            if (lane < 4) {
                redS[wid*NOUT + c]     = s0;
                redS[wid*NOUT + c + 1] = s1;
                redQ[wid*NOUT + c]     = q0;
                redQ[wid*NOUT + c + 1] = q1;
            }
        }
    }
    __syncthreads();

    if (t < NOUT) {
        float s = 0.f, q = 0.f;
        #pragma unroll
        for (int w = 0; w < 8; ++w) { s += redS[w*NOUT + t]; q += redQ[w*NOUT + t]; }
        atomicAdd(&gs[t], s);
        atomicAdd(&gq[t], q);
    }
    __threadfence();
    __syncthreads();

    __shared__ bool s_last;
    if (t == 0) s_last = (atomicAdd(ctr, 1u) == (unsigned)gridDim.x - 1u);
    __syncthreads();
    if (s_last) {
        if (t < NOUT) {
            float mean = gs[t] * (1.f/(float)M);
            float var  = gq[t] * (1.f/(float)M) - mean*mean;
            float sc   = gamma[t] * rsqrtf(var + 1e-5f);
            oscale[t] = sc;
            oshift[t] = beta[t] - mean*sc;
            gs[t] = 0.f; gq[t] = 0.f;      // replay-safe reset
        }
        if (t == 0) *ctr = 0u;
    }
}

// ---------------- SpMM: warp per row, fixed degree 21 -------------------------
template<bool GBN, bool CHEB>
__global__ void spmm_kernel(const int*   __restrict__ cols,
                            const float* __restrict__ vals,
                            const float* __restrict__ X,
                            const float* __restrict__ X0,
                            const float* __restrict__ sc_g,
                            const float* __restrict__ sh_g,
                            float* __restrict__ Yo)
{
    int warp = (blockIdx.x * blockDim.x + threadIdx.x) >> 5;
    int lane = threadIdx.x & 31;
    if (warp >= V) return;
    const int r  = warp;
    const int b  = lane >> 4;
    const int f4 = lane & 15;
    const float* Xb = X + (size_t)b*V*CMID + f4*4;

    float4 sc = make_float4(0,0,0,0), sh = make_float4(0,0,0,0);
    if (GBN || CHEB) {
        sc = *(const float4*)(sc_g + f4*4);
        sh = *(const float4*)(sh_g + f4*4);
    }

    float4 acc = make_float4(0.f, 0.f, 0.f, 0.f);
    {
        int c = __ldg(&cols[r]); float v = __ldg(&vals[r]);
        float4 xv = *(const float4*)(Xb + (size_t)c*CMID);
        if (GBN) {
            xv.x = fmaxf(fmaf(xv.x, sc.x, sh.x), 0.f);
            xv.y = fmaxf(fmaf(xv.y, sc.y, sh.y), 0.f);
            xv.z = fmaxf(fmaf(xv.z, sc.z, sh.z), 0.f);
            xv.w = fmaxf(fmaf(xv.w, sc.w, sh.w), 0.f);
        }
        acc.x += v*xv.x; acc.y += v*xv.y; acc.z += v*xv.z; acc.w += v*xv.w;
    }
    const int base = V + r*DEG;
    #pragma unroll
    for (int d = 0; d < DEG; ++d) {
        int c = __ldg(&cols[base+d]); float v = __ldg(&vals[base+d]);
        float4 xv = *(const float4*)(Xb + (size_t)c*CMID);
        if (GBN) {
            xv.x = fmaxf(fmaf(xv.x, sc.x, sh.x), 0.f);
            xv.y = fmaxf(fmaf(xv.y, sc.y, sh.y), 0.f);
            xv.z = fmaxf(fmaf(xv.z, sc.z, sh.z), 0.f);
            xv.w = fmaxf(fmaf(xv.w, sc.w, sh.w), 0.f);
        }
        acc.x += v*xv.x; acc.y += v*xv.y; acc.z += v*xv.z; acc.w += v*xv.w;
    }
    size_t o = (size_t)b*V*CMID + (size_t)r*CMID + f4*4;
    if (CHEB) {
        float4 x0 = *(const float4*)(X0 + o);
        x0.x = fmaxf(fmaf(x0.x, sc.x, sh.x), 0.f);
        x0.y = fmaxf(fmaf(x0.y, sc.y, sh.y), 0.f);
        x0.z = fmaxf(fmaf(x0.z, sc.z, sh.z), 0.f);
        x0.w = fmaxf(fmaf(x0.w, sc.w, sh.w), 0.f);
        acc.x = 2.f*acc.x - x0.x; acc.y = 2.f*acc.y - x0.y;
        acc.z = 2.f*acc.z - x0.z; acc.w = 2.f*acc.w - x0.w;
    }
    *(float4*)(Yo + o) = acc;
}

// ---------------- fused BN apply + ReLU (final layer only) --------------------
template<int C>
__global__ void bnrelu_kernel(const float* __restrict__ Yin,
                              float* __restrict__ H,
                              const float* __restrict__ scale,
                              const float* __restrict__ shift)
{
    int i4 = blockIdx.x * blockDim.x + threadIdx.x;
    constexpr int TOT4 = M*C/4;
    if (i4 >= TOT4) return;
    int c4 = i4 % (C/4);
    float4 v  = ((const float4*)Yin)[i4];
    float4 sc = ((const float4*)scale)[c4];
    float4 sh = ((const float4*)shift)[c4];
    v.x = fmaxf(fmaf(v.x, sc.x, sh.x), 0.f);
    v.y = fmaxf(fmaf(v.y, sc.y, sh.y), 0.f);
    v.z = fmaxf(fmaf(v.z, sc.z, sh.z), 0.f);
    v.w = fmaxf(fmaf(v.w, sc.w, sh.w), 0.f);
    ((float4*)H)[i4] = v;
}

// ------------------------------------------------------------------------------
extern "C" void kernel_launch(void* const* d_in, const int* in_sizes, int n_in,
                              void* d_out, int out_size)
{
    const float* x    = (const float*)d_in[0];
    const int*   cols = (const int*)  d_in[2];
    const float* vals = (const float*)d_in[3];
    const float* W1   = (const float*)d_in[4];
    const float* b1   = (const float*)d_in[5];
    const float* g1   = (const float*)d_in[6];
    const float* be1  = (const float*)d_in[7];
    const float* W2   = (const float*)d_in[8];
    const float* b2   = (const float*)d_in[9];
    const float* g2   = (const float*)d_in[10];
    const float* be2  = (const float*)d_in[11];
    const float* W3   = (const float*)d_in[12];
    const float* b3   = (const float*)d_in[13];
    const float* g3   = (const float*)d_in[14];
    const float* be3  = (const float*)d_in[15];
    float* out = (float*)d_out;

    float *y1, *t1, *t2, *y2, *gsum, *gsq, *gscale, *gshift;
    unsigned int* ctr;
    cudaGetSymbolAddress((void**)&y1, g_y1);
    cudaGetSymbolAddress((void**)&t1, g_t1);
    cudaGetSymbolAddress((void**)&t2, g_t2);
    cudaGetSymbolAddress((void**)&y2, g_y2);
    cudaGetSymbolAddress((void**)&gsum,   g_sum);
    cudaGetSymbolAddress((void**)&gsq,    g_sq);
    cudaGetSymbolAddress((void**)&gscale, g_scale);
    cudaGetSymbolAddress((void**)&gshift, g_shift);
    cudaGetSymbolAddress((void**)&ctr,    g_ctr);

    const int smem1 = 2*(128*(128+8)*2) + 2*(64*(128+8)*2);    // 104448
    const int smem2 = 2*(128*(192+8)*2) + 2*(64*(192+8)*2);    // 153600
    const int smem3 = 2*(128*(64+8)*2)  + 2*(128*(64+8)*2);    //  73728
    cudaFuncSetAttribute(gemm_mma<128, 64, 1, false>, cudaFuncAttributeMaxDynamicSharedMemorySize, smem1);
    cudaFuncSetAttribute(gemm_mma< 64, 64, 3, true >, cudaFuncAttributeMaxDynamicSharedMemorySize, smem2);
    cudaFuncSetAttribute(gemm_mma< 64,128, 1, true >, cudaFuncAttributeMaxDynamicSharedMemorySize, smem3);

    const int GEMM_GRID   = M / 128;        // 768
    const int SPMM_GRID   = V * 32 / 256;   // 6144
    const int BNR_GRID128 = M*CIN/4/256;    // 12288

    // ---- layer 1: y1 = x @ W1 + b1 ; fused stats+finalize -> gscale0/gshift0 ----
    gemm_mma<128, 64, 1, false><<<GEMM_GRID, 256, smem1>>>(
        x, nullptr, nullptr, W1, b1, nullptr, nullptr, y1,
        g1, be1, gsum + 0, gsq + 0, gscale + 0, gshift + 0, ctr + 0);

    // ---- layer 2: Chebyshev K=3, h1 = bnrelu(y1) materialized on the fly ----
    spmm_kernel<true , false><<<SPMM_GRID, 256>>>(cols, vals, y1, nullptr, gscale + 0, gshift + 0, t1);
    spmm_kernel<false, true ><<<SPMM_GRID, 256>>>(cols, vals, t1, y1,      gscale + 0, gshift + 0, t2);
    gemm_mma<64, 64, 3, true><<<GEMM_GRID, 256, smem2>>>(
        y1, t1, t2, W2, b2, gscale + 0, gshift + 0, y2,
        g2, be2, gsum + 128, gsq + 128, gscale + 128, gshift + 128, ctr + 1);

    // ---- layer 3: out = bnrelu( bnrelu(y2) @ W3 + b3 ) ----
    gemm_mma<64, 128, 1, true><<<GEMM_GRID, 256, smem3>>>(
        y2, nullptr, nullptr, W3, b3, gscale + 128, gshift + 128, out,
        g3, be3, gsum + 256, gsq + 256, gscale + 256, gshift + 256, ctr + 2);
    bnrelu_kernel<CIN><<<BNR_GRID128, 256>>>(out, out, gscale + 256, gshift + 256);
}

// round 6
// speedup vs baseline: 1.2301x; 1.2301x over previous
#include <cuda_runtime.h>
#include <cuda_bf16.h>
#include <math.h>
#include <stdint.h>

#define V     49152
#define BATCH 2
#define M     (BATCH*V)      // 98304
#define DEG   20
#define CIN   128
#define CMID  64

// ---------------- scratch (device globals; zero-initialized) ------------------
__device__ __align__(128) float g_y1[M*CMID];
__device__ __align__(128) float g_t1[M*CMID];
__device__ __align__(128) float g_t2[M*CMID];
__device__ __align__(128) float g_y2[M*CMID];
__device__ __align__(128) float g_sum[3*128];
__device__ __align__(128) float g_sq [3*128];
__device__ __align__(128) float g_scale[3*128];
__device__ __align__(128) float g_shift[3*128];
__device__ unsigned int g_ctr[3];

// ---------------- PTX helpers --------------------------------------------------
__device__ __forceinline__ void mma16816(float* c, const uint32_t* a, const uint32_t* b) {
    asm volatile(
        "mma.sync.aligned.m16n8k16.row.col.f32.bf16.bf16.f32 "
        "{%0,%1,%2,%3}, {%4,%5,%6,%7}, {%8,%9}, {%0,%1,%2,%3};"
        : "+f"(c[0]), "+f"(c[1]), "+f"(c[2]), "+f"(c[3])
        : "r"(a[0]), "r"(a[1]), "r"(a[2]), "r"(a[3]), "r"(b[0]), "r"(b[1]));
}
__device__ __forceinline__ void ldsm_x4(uint32_t* r, uint32_t addr) {
    asm volatile("ldmatrix.sync.aligned.m8n8.x4.shared.b16 {%0,%1,%2,%3}, [%4];"
        : "=r"(r[0]), "=r"(r[1]), "=r"(r[2]), "=r"(r[3]) : "r"(addr));
}
__device__ __forceinline__ void ldsm_x2(uint32_t* r, uint32_t addr) {
    asm volatile("ldmatrix.sync.aligned.m8n8.x2.shared.b16 {%0,%1}, [%2];"
        : "=r"(r[0]), "=r"(r[1]) : "r"(addr));
}
__device__ __forceinline__ uint32_t smem_u32(const void* p) {
    uint32_t a;
    asm("{ .reg .u64 t; cvta.to.shared.u64 t, %1; cvt.u32.u64 %0, t; }" : "=r"(a) : "l"(p));
    return a;
}
__device__ __forceinline__ uint32_t pack2(__nv_bfloat16 a, __nv_bfloat16 b) {
    __nv_bfloat162 h; h.x = a; h.y = b;
    return *reinterpret_cast<uint32_t*>(&h);
}

// ---------------- tensor-core GEMM (HMMA, chunked, ldmatrix) -------------------
// Y[128-row tile, NOUT] = sum_s A_s[tile, K] @ W[s*K.., NOUT] + bias
// bf16 hi/lo split (hi*hi + hi*lo + lo*hi), fp32 accumulators.
// K staged through a single reused 64-col A buffer (chunk loop) -> small smem,
// 2-3 CTAs/SM. Fragments loaded via ldmatrix. Fused BN-stats epilogue; last
// block computes scale/shift and resets accumulators (replay-safe).
template<int K, int NOUT, int NSRC, bool BN0>
__global__ void __launch_bounds__(256) gemm_mma(
    const float* __restrict__ A0, const float* __restrict__ A1, const float* __restrict__ A2,
    const float* __restrict__ W, const float* __restrict__ bias,
    const float* __restrict__ bsc, const float* __restrict__ bsh,
    float* __restrict__ Y,
    const float* __restrict__ gamma, const float* __restrict__ beta,
    float* __restrict__ gs, float* __restrict__ gq,
    float* __restrict__ oscale, float* __restrict__ oshift,
    unsigned int* __restrict__ ctr)
{
    constexpr int KT   = NSRC*K;
    constexpr int NCH  = KT/64;               // 64-col chunks
    constexpr int SA   = 72;                  // padded row stride (bf16 elems)
    constexpr int WCH  = NOUT*SA*2;           // bytes per W chunk (hi or lo)
    constexpr int ACH  = 128*SA*2;            // bytes per A buffer (hi or lo)
    constexpr int OFF_A = NCH*2*WCH;

    extern __shared__ char smc[];
    const uint32_t sbase = smem_u32(smc);

    const int t    = threadIdx.x;
    const int wid  = t >> 5, lane = t & 31;
    const int row0 = blockIdx.x * 128;
    const int g    = lane >> 2, tg = lane & 3;
    const int rb   = wid*16;

    // ---- stage W: Wt[n][k] = W[kt][n] per chunk, hi/lo ----
    for (int i = t; i < KT*NOUT; i += 256) {
        int n = i % NOUT, kt = i / NOUT;
        int c = kt >> 6, kk = kt & 63;
        float w = W[i];
        __nv_bfloat16 h = __float2bfloat16(w);
        *(__nv_bfloat16*)(smc + c*2*WCH + (n*SA + kk)*2)       = h;
        *(__nv_bfloat16*)(smc + c*2*WCH + WCH + (n*SA + kk)*2) =
            __float2bfloat16(w - __bfloat162float(h));
    }

    constexpr int NB = NOUT/8;
    float acc[NB][4];
    #pragma unroll
    for (int nb = 0; nb < NB; ++nb)
        acc[nb][0] = acc[nb][1] = acc[nb][2] = acc[nb][3] = 0.f;

    // per-lane ldmatrix addresses
    const uint32_t aHi  = sbase + OFF_A + ((rb + (lane & 15))*SA + (lane >> 4)*8)*2;
    const uint32_t wlan = (((lane & 7)*SA + ((lane >> 3) & 1)*8))*2;

    #pragma unroll
    for (int c = 0; c < NCH; ++c) {
        const int s  = (c*64) / K;
        const int ko = (c*64) % K;
        const float* A = (s == 0) ? A0 : ((s == 1) ? A1 : A2);

        __syncthreads();   // W staged (c==0) / previous chunk consumed
        for (int i = t; i < 128*16; i += 256) {
            int r = i >> 4, c4 = i & 15;
            float4 v = *(const float4*)(A + (size_t)(row0 + r)*K + ko + c4*4);
            if (BN0 && s == 0) {
                float4 sc = *(const float4*)(bsc + ko + c4*4);
                float4 sh = *(const float4*)(bsh + ko + c4*4);
                v.x = fmaxf(fmaf(v.x, sc.x, sh.x), 0.f);
                v.y = fmaxf(fmaf(v.y, sc.y, sh.y), 0.f);
                v.z = fmaxf(fmaf(v.z, sc.z, sh.z), 0.f);
                v.w = fmaxf(fmaf(v.w, sc.w, sh.w), 0.f);
            }
            __nv_bfloat16 hx = __float2bfloat16(v.x), hy = __float2bfloat16(v.y);
            __nv_bfloat16 hz = __float2bfloat16(v.z), hw = __float2bfloat16(v.w);
            uint32_t* dh = (uint32_t*)(smc + OFF_A + (r*SA + c4*4)*2);
            uint32_t* dl = (uint32_t*)(smc + OFF_A + ACH + (r*SA + c4*4)*2);
            dh[0] = pack2(hx, hy);
            dh[1] = pack2(hz, hw);
            dl[0] = pack2(__float2bfloat16(v.x - __bfloat162float(hx)),
                          __float2bfloat16(v.y - __bfloat162float(hy)));
            dl[1] = pack2(__float2bfloat16(v.z - __bfloat162float(hz)),
                          __float2bfloat16(v.w - __bfloat162float(hw)));
        }
        __syncthreads();

        const uint32_t wch = sbase + c*2*WCH + wlan;
        #pragma unroll
        for (int kk = 0; kk < 4; ++kk) {
            uint32_t ah[4], al[4];
            ldsm_x4(ah, aHi + kk*32);
            ldsm_x4(al, aHi + ACH + kk*32);
            #pragma unroll
            for (int nb = 0; nb < NB; ++nb) {
                uint32_t bh[2], bl[2];
                uint32_t wa = wch + nb*8*SA*2 + kk*32;
                ldsm_x2(bh, wa);
                ldsm_x2(bl, wa + WCH);
                mma16816(acc[nb], ah, bh);   // hi*hi
                mma16816(acc[nb], ah, bl);   // hi*lo
                mma16816(acc[nb], al, bh);   // lo*hi
            }
        }
    }

    __syncthreads();   // compute done -> smem reusable for stats reduction
    float* redS = (float*)smc;               // [8][NOUT]
    float* redQ = (float*)smc + 8*NOUT;      // [8][NOUT]

    // ---- store + per-warp column partials ----
    {
        float* y0 = Y + (size_t)(row0 + rb + g)*NOUT;
        float* y8 = Y + (size_t)(row0 + rb + g + 8)*NOUT;
        #pragma unroll
        for (int nb = 0; nb < NB; ++nb) {
            int c = nb*8 + tg*2;
            float2 bb = __ldg((const float2*)(bias + c));
            float y00 = acc[nb][0] + bb.x, y01 = acc[nb][1] + bb.y;
            float y80 = acc[nb][2] + bb.x, y81 = acc[nb][3] + bb.y;
            *(float2*)(y0 + c) = make_float2(y00, y01);
            *(float2*)(y8 + c) = make_float2(y80, y81);
            float s0 = y00 + y80, q0 = y00*y00 + y80*y80;
            float s1 = y01 + y81, q1 = y01*y01 + y81*y81;
            #pragma unroll
            for (int off = 4; off <= 16; off <<= 1) {
                s0 += __shfl_xor_sync(0xffffffffu, s0, off);
                q0 += __shfl_xor_sync(0xffffffffu, q0, off);
                s1 += __shfl_xor_sync(0xffffffffu, s1, off);
                q1 += __shfl_xor_sync(0xffffffffu, q1, off);
            }
            if (lane < 4) {
                redS[wid*NOUT + c]     = s0;
                redS[wid*NOUT + c + 1] = s1;
                redQ[wid*NOUT + c]     = q0;
                redQ[wid*NOUT + c + 1] = q1;
            }
        }
    }
    __syncthreads();

    if (t < NOUT) {
        float s = 0.f, q = 0.f;
        #pragma unroll
        for (int w = 0; w < 8; ++w) { s += redS[w*NOUT + t]; q += redQ[w*NOUT + t]; }
        atomicAdd(&gs[t], s);
        atomicAdd(&gq[t], q);
    }
    __threadfence();
    __syncthreads();

    __shared__ bool s_last;
    if (t == 0) s_last = (atomicAdd(ctr, 1u) == (unsigned)gridDim.x - 1u);
    __syncthreads();
    if (s_last) {
        if (t < NOUT) {
            float mean = gs[t] * (1.f/(float)M);
            float var  = gq[t] * (1.f/(float)M) - mean*mean;
            float sc   = gamma[t] * rsqrtf(var + 1e-5f);
            oscale[t] = sc;
            oshift[t] = beta[t] - mean*sc;
            gs[t] = 0.f; gq[t] = 0.f;      // replay-safe reset
        }
        if (t == 0) *ctr = 0u;
    }
}

// ---------------- SpMM: warp per row, fixed degree 21 -------------------------
template<bool GBN, bool CHEB>
__global__ void spmm_kernel(const int*   __restrict__ cols,
                            const float* __restrict__ vals,
                            const float* __restrict__ X,
                            const float* __restrict__ X0,
                            const float* __restrict__ sc_g,
                            const float* __restrict__ sh_g,
                            float* __restrict__ Yo)
{
    int warp = (blockIdx.x * blockDim.x + threadIdx.x) >> 5;
    int lane = threadIdx.x & 31;
    if (warp >= V) return;
    const int r  = warp;
    const int b  = lane >> 4;
    const int f4 = lane & 15;
    const float* Xb = X + (size_t)b*V*CMID + f4*4;

    float4 sc = make_float4(0,0,0,0), sh = make_float4(0,0,0,0);
    if (GBN || CHEB) {
        sc = *(const float4*)(sc_g + f4*4);
        sh = *(const float4*)(sh_g + f4*4);
    }

    float4 acc = make_float4(0.f, 0.f, 0.f, 0.f);
    {
        int c = __ldg(&cols[r]); float v = __ldg(&vals[r]);
        float4 xv = *(const float4*)(Xb + (size_t)c*CMID);
        if (GBN) {
            xv.x = fmaxf(fmaf(xv.x, sc.x, sh.x), 0.f);
            xv.y = fmaxf(fmaf(xv.y, sc.y, sh.y), 0.f);
            xv.z = fmaxf(fmaf(xv.z, sc.z, sh.z), 0.f);
            xv.w = fmaxf(fmaf(xv.w, sc.w, sh.w), 0.f);
        }
        acc.x += v*xv.x; acc.y += v*xv.y; acc.z += v*xv.z; acc.w += v*xv.w;
    }
    const int base = V + r*DEG;
    #pragma unroll
    for (int d = 0; d < DEG; ++d) {
        int c = __ldg(&cols[base+d]); float v = __ldg(&vals[base+d]);
        float4 xv = *(const float4*)(Xb + (size_t)c*CMID);
        if (GBN) {
            xv.x = fmaxf(fmaf(xv.x, sc.x, sh.x), 0.f);
            xv.y = fmaxf(fmaf(xv.y, sc.y, sh.y), 0.f);
            xv.z = fmaxf(fmaf(xv.z, sc.z, sh.z), 0.f);
            xv.w = fmaxf(fmaf(xv.w, sc.w, sh.w), 0.f);
        }
        acc.x += v*xv.x; acc.y += v*xv.y; acc.z += v*xv.z; acc.w += v*xv.w;
    }
    size_t o = (size_t)b*V*CMID + (size_t)r*CMID + f4*4;
    if (CHEB) {
        float4 x0 = *(const float4*)(X0 + o);
        x0.x = fmaxf(fmaf(x0.x, sc.x, sh.x), 0.f);
        x0.y = fmaxf(fmaf(x0.y, sc.y, sh.y), 0.f);
        x0.z = fmaxf(fmaf(x0.z, sc.z, sh.z), 0.f);
        x0.w = fmaxf(fmaf(x0.w, sc.w, sh.w), 0.f);
        acc.x = 2.f*acc.x - x0.x; acc.y = 2.f*acc.y - x0.y;
        acc.z = 2.f*acc.z - x0.z; acc.w = 2.f*acc.w - x0.w;
    }
    *(float4*)(Yo + o) = acc;
}

// ---------------- fused BN apply + ReLU (final layer only) --------------------
template<int C>
__global__ void bnrelu_kernel(const float* __restrict__ Yin,
                              float* __restrict__ H,
                              const float* __restrict__ scale,
                              const float* __restrict__ shift)
{
    int i4 = blockIdx.x * blockDim.x + threadIdx.x;
    constexpr int TOT4 = M*C/4;
    if (i4 >= TOT4) return;
    int c4 = i4 % (C/4);
    float4 v  = ((const float4*)Yin)[i4];
    float4 sc = ((const float4*)scale)[c4];
    float4 sh = ((const float4*)shift)[c4];
    v.x = fmaxf(fmaf(v.x, sc.x, sh.x), 0.f);
    v.y = fmaxf(fmaf(v.y, sc.y, sh.y), 0.f);
    v.z = fmaxf(fmaf(v.z, sc.z, sh.z), 0.f);
    v.w = fmaxf(fmaf(v.w, sc.w, sh.w), 0.f);
    ((float4*)H)[i4] = v;
}

// ------------------------------------------------------------------------------
extern "C" void kernel_launch(void* const* d_in, const int* in_sizes, int n_in,
                              void* d_out, int out_size)
{
    const float* x    = (const float*)d_in[0];
    const int*   cols = (const int*)  d_in[2];
    const float* vals = (const float*)d_in[3];
    const float* W1   = (const float*)d_in[4];
    const float* b1   = (const float*)d_in[5];
    const float* g1   = (const float*)d_in[6];
    const float* be1  = (const float*)d_in[7];
    const float* W2   = (const float*)d_in[8];
    const float* b2   = (const float*)d_in[9];
    const float* g2   = (const float*)d_in[10];
    const float* be2  = (const float*)d_in[11];
    const float* W3   = (const float*)d_in[12];
    const float* b3   = (const float*)d_in[13];
    const float* g3   = (const float*)d_in[14];
    const float* be3  = (const float*)d_in[15];
    float* out = (float*)d_out;

    float *y1, *t1, *t2, *y2, *gsum, *gsq, *gscale, *gshift;
    unsigned int* ctr;
    cudaGetSymbolAddress((void**)&y1, g_y1);
    cudaGetSymbolAddress((void**)&t1, g_t1);
    cudaGetSymbolAddress((void**)&t2, g_t2);
    cudaGetSymbolAddress((void**)&y2, g_y2);
    cudaGetSymbolAddress((void**)&gsum,   g_sum);
    cudaGetSymbolAddress((void**)&gsq,    g_sq);
    cudaGetSymbolAddress((void**)&gscale, g_scale);
    cudaGetSymbolAddress((void**)&gshift, g_shift);
    cudaGetSymbolAddress((void**)&ctr,    g_ctr);

    // smem: NCH*2*W_chunk + 2*A_chunk  (SA=72)
    const int smem1 = 2*2*(64*72*2)  + 2*(128*72*2);    //  73728
    const int smem2 = 3*2*(64*72*2)  + 2*(128*72*2);    //  92160
    const int smem3 = 1*2*(128*72*2) + 2*(128*72*2);    //  73728
    cudaFuncSetAttribute(gemm_mma<128, 64, 1, false>, cudaFuncAttributeMaxDynamicSharedMemorySize, smem1);
    cudaFuncSetAttribute(gemm_mma< 64, 64, 3, true >, cudaFuncAttributeMaxDynamicSharedMemorySize, smem2);
    cudaFuncSetAttribute(gemm_mma< 64,128, 1, true >, cudaFuncAttributeMaxDynamicSharedMemorySize, smem3);

    const int GEMM_GRID   = M / 128;        // 768
    const int SPMM_GRID   = V * 32 / 256;   // 6144
    const int BNR_GRID128 = M*CIN/4/256;    // 12288

    // ---- layer 1: y1 = x @ W1 + b1 ; fused stats+finalize ----
    gemm_mma<128, 64, 1, false><<<GEMM_GRID, 256, smem1>>>(
        x, nullptr, nullptr, W1, b1, nullptr, nullptr, y1,
        g1, be1, gsum + 0, gsq + 0, gscale + 0, gshift + 0, ctr + 0);

    // ---- layer 2: Chebyshev K=3, h1 = bnrelu(y1) materialized on the fly ----
    spmm_kernel<true , false><<<SPMM_GRID, 256>>>(cols, vals, y1, nullptr, gscale + 0, gshift + 0, t1);
    spmm_kernel<false, true ><<<SPMM_GRID, 256>>>(cols, vals, t1, y1,      gscale + 0, gshift + 0, t2);
    gemm_mma<64, 64, 3, true><<<GEMM_GRID, 256, smem2>>>(
        y1, t1, t2, W2, b2, gscale + 0, gshift + 0, y2,
        g2, be2, gsum + 128, gsq + 128, gscale + 128, gshift + 128, ctr + 1);

    // ---- layer 3: out = bnrelu( bnrelu(y2) @ W3 + b3 ) ----
    gemm_mma<64, 128, 1, true><<<GEMM_GRID, 256, smem3>>>(
        y2, nullptr, nullptr, W3, b3, gscale + 128, gshift + 128, out,
        g3, be3, gsum + 256, gsq + 256, gscale + 256, gshift + 256, ctr + 2);
    bnrelu_kernel<CIN><<<BNR_GRID128, 256>>>(out, out, gscale + 256, gshift + 256);
}

// round 8
// speedup vs baseline: 1.4045x; 1.1418x over previous
#include <cuda_runtime.h>
#include <cuda_bf16.h>
#include <cuda_fp16.h>
#include <math.h>
#include <stdint.h>

#define V     49152
#define BATCH 2
#define M     (BATCH*V)      // 98304
#define DEG   20
#define CIN   128
#define CMID  64

// ---------------- scratch (device globals; zero-initialized) ------------------
__device__ __align__(128) float  g_y1[M*CMID];
__device__ __align__(128) float  g_y2[M*CMID];
__device__ __align__(128) __half g_h1h[M*CMID];
__device__ __align__(128) __half g_t1h[M*CMID];
__device__ __align__(128) __half g_t2h[M*CMID];
__device__ __align__(128) float g_sum[3*128];
__device__ __align__(128) float g_sq [3*128];
__device__ __align__(128) float g_scale[3*128];
__device__ __align__(128) float g_shift[3*128];
__device__ unsigned int g_ctr[3];

// ---------------- PTX helpers --------------------------------------------------
__device__ __forceinline__ void mma16816(float* c, const uint32_t* a, const uint32_t* b) {
    asm volatile(
        "mma.sync.aligned.m16n8k16.row.col.f32.bf16.bf16.f32 "
        "{%0,%1,%2,%3}, {%4,%5,%6,%7}, {%8,%9}, {%0,%1,%2,%3};"
        : "+f"(c[0]), "+f"(c[1]), "+f"(c[2]), "+f"(c[3])
        : "r"(a[0]), "r"(a[1]), "r"(a[2]), "r"(a[3]), "r"(b[0]), "r"(b[1]));
}
__device__ __forceinline__ void ldsm_x4(uint32_t* r, uint32_t addr) {
    asm volatile("ldmatrix.sync.aligned.m8n8.x4.shared.b16 {%0,%1,%2,%3}, [%4];"
        : "=r"(r[0]), "=r"(r[1]), "=r"(r[2]), "=r"(r[3]) : "r"(addr));
}
__device__ __forceinline__ void ldsm_x2(uint32_t* r, uint32_t addr) {
    asm volatile("ldmatrix.sync.aligned.m8n8.x2.shared.b16 {%0,%1}, [%2];"
        : "=r"(r[0]), "=r"(r[1]) : "r"(addr));
}
__device__ __forceinline__ uint32_t smem_u32(const void* p) {
    uint32_t a;
    asm("{ .reg .u64 t; cvta.to.shared.u64 t, %1; cvt.u32.u64 %0, t; }" : "=r"(a) : "l"(p));
    return a;
}
__device__ __forceinline__ uint32_t pack2(__nv_bfloat16 a, __nv_bfloat16 b) {
    __nv_bfloat162 h; h.x = a; h.y = b;
    return *reinterpret_cast<uint32_t*>(&h);
}
__device__ __forceinline__ void split2(float a, float b, uint32_t& hi, uint32_t& lo) {
    __nv_bfloat16 ha = __float2bfloat16(a), hb = __float2bfloat16(b);
    hi = pack2(ha, hb);
    lo = pack2(__float2bfloat16(a - __bfloat162float(ha)),
               __float2bfloat16(b - __bfloat162float(hb)));
}

// ---------------- tensor-core GEMM (HMMA, chunked, ldmatrix) -------------------
// Y[128-row tile, NOUT] = sum_s A_s[tile, K] @ W[s*K.., NOUT] + bias
// bf16 hi/lo split (hi*hi + hi*lo + lo*hi), fp32 accumulators.
// F16: sources are pre-activated __half (BN0 ignored). Fused BN-stats epilogue;
// last block computes scale/shift and resets accumulators (replay-safe).
template<int K, int NOUT, int NSRC, bool BN0, bool F16>
__global__ void __launch_bounds__(256) gemm_mma(
    const void* __restrict__ A0v, const void* __restrict__ A1v, const void* __restrict__ A2v,
    const float* __restrict__ W, const float* __restrict__ bias,
    const float* __restrict__ bsc, const float* __restrict__ bsh,
    float* __restrict__ Y,
    const float* __restrict__ gamma, const float* __restrict__ beta,
    float* __restrict__ gs, float* __restrict__ gq,
    float* __restrict__ oscale, float* __restrict__ oshift,
    unsigned int* __restrict__ ctr)
{
    constexpr int KT   = NSRC*K;
    constexpr int NCH  = KT/64;               // 64-col chunks
    constexpr int SA   = 72;                  // padded row stride (bf16 elems)
    constexpr int WCH  = NOUT*SA*2;           // bytes per W chunk (hi or lo)
    constexpr int ACH  = 128*SA*2;            // bytes per A buffer (hi or lo)
    constexpr int OFF_A = NCH*2*WCH;

    extern __shared__ char smc[];
    const uint32_t sbase = smem_u32(smc);

    const int t    = threadIdx.x;
    const int wid  = t >> 5, lane = t & 31;
    const int row0 = blockIdx.x * 128;
    const int g    = lane >> 2, tg = lane & 3;
    const int rb   = wid*16;

    // ---- stage W: Wt[n][k] = W[kt][n] per chunk, hi/lo ----
    for (int i = t; i < KT*NOUT; i += 256) {
        int n = i % NOUT, kt = i / NOUT;
        int c = kt >> 6, kk = kt & 63;
        float w = W[i];
        __nv_bfloat16 h = __float2bfloat16(w);
        *(__nv_bfloat16*)(smc + c*2*WCH + (n*SA + kk)*2)       = h;
        *(__nv_bfloat16*)(smc + c*2*WCH + WCH + (n*SA + kk)*2) =
            __float2bfloat16(w - __bfloat162float(h));
    }

    constexpr int NB = NOUT/8;
    float acc[NB][4];
    #pragma unroll
    for (int nb = 0; nb < NB; ++nb)
        acc[nb][0] = acc[nb][1] = acc[nb][2] = acc[nb][3] = 0.f;

    const uint32_t aHi  = sbase + OFF_A + ((rb + (lane & 15))*SA + (lane >> 4)*8)*2;
    const uint32_t wlan = (((lane & 7)*SA + ((lane >> 3) & 1)*8))*2;

    #pragma unroll
    for (int c = 0; c < NCH; ++c) {
        const int s  = (c*64) / K;
        const int ko = (c*64) % K;
        const void* Av = (s == 0) ? A0v : ((s == 1) ? A1v : A2v);

        __syncthreads();   // W staged (c==0) / previous chunk consumed
        if (F16) {
            const __half* A = (const __half*)Av;
            for (int i = t; i < 128*8; i += 256) {
                int r = i >> 3, c8 = i & 7;
                uint4 u = *(const uint4*)(A + (size_t)(row0 + r)*K + ko + c8*8);
                const __half2* hp = (const __half2*)&u;
                uint32_t dh[4], dl[4];
                #pragma unroll
                for (int j = 0; j < 4; ++j) {
                    float2 f = __half22float2(hp[j]);
                    split2(f.x, f.y, dh[j], dl[j]);
                }
                *(uint4*)(smc + OFF_A + (r*SA + c8*8)*2)       = make_uint4(dh[0], dh[1], dh[2], dh[3]);
                *(uint4*)(smc + OFF_A + ACH + (r*SA + c8*8)*2) = make_uint4(dl[0], dl[1], dl[2], dl[3]);
            }
        } else {
            const float* A = (const float*)Av;
            for (int i = t; i < 128*16; i += 256) {
                int r = i >> 4, c4 = i & 15;
                float4 v = *(const float4*)(A + (size_t)(row0 + r)*K + ko + c4*4);
                if (BN0 && s == 0) {
                    float4 sc = *(const float4*)(bsc + ko + c4*4);
                    float4 sh = *(const float4*)(bsh + ko + c4*4);
                    v.x = fmaxf(fmaf(v.x, sc.x, sh.x), 0.f);
                    v.y = fmaxf(fmaf(v.y, sc.y, sh.y), 0.f);
                    v.z = fmaxf(fmaf(v.z, sc.z, sh.z), 0.f);
                    v.w = fmaxf(fmaf(v.w, sc.w, sh.w), 0.f);
                }
                uint32_t* dh = (uint32_t*)(smc + OFF_A + (r*SA + c4*4)*2);
                uint32_t* dl = (uint32_t*)(smc + OFF_A + ACH + (r*SA + c4*4)*2);
                split2(v.x, v.y, dh[0], dl[0]);
                split2(v.z, v.w, dh[1], dl[1]);
            }
        }
        __syncthreads();

        const uint32_t wch = sbase + c*2*WCH + wlan;
        #pragma unroll
        for (int kk = 0; kk < 4; ++kk) {
            uint32_t ah[4], al[4];
            ldsm_x4(ah, aHi + kk*32);
            ldsm_x4(al, aHi + ACH + kk*32);
            #pragma unroll
            for (int nb = 0; nb < NB; ++nb) {
                uint32_t bh[2], bl[2];
                uint32_t wa = wch + nb*8*SA*2 + kk*32;
                ldsm_x2(bh, wa);
                ldsm_x2(bl, wa + WCH);
                mma16816(acc[nb], ah, bh);   // hi*hi
                mma16816(acc[nb], ah, bl);   // hi*lo
                mma16816(acc[nb], al, bh);   // lo*hi
            }
        }
    }

    __syncthreads();   // compute done -> smem reusable for stats reduction
    float* redS = (float*)smc;               // [8][NOUT]
    float* redQ = (float*)smc + 8*NOUT;      // [8][NOUT]

    // ---- store + per-warp column partials ----
    {
        float* y0 = Y + (size_t)(row0 + rb + g)*NOUT;
        float* y8 = Y + (size_t)(row0 + rb + g + 8)*NOUT;
        #pragma unroll
        for (int nb = 0; nb < NB; ++nb) {
            int c = nb*8 + tg*2;
            float2 bb = __ldg((const float2*)(bias + c));
            float y00 = acc[nb][0] + bb.x, y01 = acc[nb][1] + bb.y;
            float y80 = acc[nb][2] + bb.x, y81 = acc[nb][3] + bb.y;
            *(float2*)(y0 + c) = make_float2(y00, y01);
            *(float2*)(y8 + c) = make_float2(y80, y81);
            float s0 = y00 + y80, q0 = y00*y00 + y80*y80;
            float s1 = y01 + y81, q1 = y01*y01 + y81*y81;
            #pragma unroll
            for (int off = 4; off <= 16; off <<= 1) {
                s0 += __shfl_xor_sync(0xffffffffu, s0, off);
                q0 += __shfl_xor_sync(0xffffffffu, q0, off);
                s1 += __shfl_xor_sync(0xffffffffu, s1, off);
                q1 += __shfl_xor_sync(0xffffffffu, q1, off);
            }
            if (lane < 4) {
                redS[wid*NOUT + c]     = s0;
                redS[wid*NOUT + c + 1] = s1;
                redQ[wid*NOUT + c]     = q0;
                redQ[wid*NOUT + c + 1] = q1;
            }
        }
    }
    __syncthreads();

    if (t < NOUT) {
        float s = 0.f, q = 0.f;
        #pragma unroll
        for (int w = 0; w < 8; ++w) { s += redS[w*NOUT + t]; q += redQ[w*NOUT + t]; }
        atomicAdd(&gs[t], s);
        atomicAdd(&gq[t], q);
    }
    __threadfence();
    __syncthreads();

    __shared__ bool s_last;
    if (t == 0) s_last = (atomicAdd(ctr, 1u) == (unsigned)gridDim.x - 1u);
    __syncthreads();
    if (s_last) {
        if (t < NOUT) {
            float mean = gs[t] * (1.f/(float)M);
            float var  = gq[t] * (1.f/(float)M) - mean*mean;
            float sc   = gamma[t] * rsqrtf(var + 1e-5f);
            oscale[t] = sc;
            oshift[t] = beta[t] - mean*sc;
            gs[t] = 0.f; gq[t] = 0.f;      // replay-safe reset
        }
        if (t == 0) *ctr = 0u;
    }
}

// ---------------- SpMM fp16: 2 rows/warp, 8 fp16 channels/lane -----------------
// lane: row = warp*2 + (lane>>4); b = (lane>>3)&1; f8 = lane&7.
// CHEB: out = 2*acc - X0h (pre-activated).
template<bool CHEB>
__global__ void spmm_f16(const int*   __restrict__ cols,
                         const float* __restrict__ vals,
                         const __half* __restrict__ X,
                         const __half* __restrict__ X0h,
                         __half* __restrict__ Yo)
{
    int warp = (blockIdx.x * blockDim.x + threadIdx.x) >> 5;
    int lane = threadIdx.x & 31;
    int r = warp*2 + (lane >> 4);
    if (r >= V) return;
    const int b  = (lane >> 3) & 1;
    const int f8 = lane & 7;
    const __half* Xb = X + (size_t)b*V*CMID + f8*8;

    float acc[8];
    #pragma unroll
    for (int j = 0; j < 8; ++j) acc[j] = 0.f;

    {
        int c = __ldg(&cols[r]); float v = __ldg(&vals[r]);
        uint4 u = *(const uint4*)(Xb + (size_t)c*CMID);
        const __half2* hp = (const __half2*)&u;
        #pragma unroll
        for (int j = 0; j < 4; ++j) {
            float2 f = __half22float2(hp[j]);
            acc[2*j]   += v*f.x;
            acc[2*j+1] += v*f.y;
        }
    }
    const int base = V + r*DEG;
    #pragma unroll
    for (int d = 0; d < DEG; ++d) {
        int c = __ldg(&cols[base+d]); float v = __ldg(&vals[base+d]);
        uint4 u = *(const uint4*)(Xb + (size_t)c*CMID);
        const __half2* hp = (const __half2*)&u;
        #pragma unroll
        for (int j = 0; j < 4; ++j) {
            float2 f = __half22float2(hp[j]);
            acc[2*j]   += v*f.x;
            acc[2*j+1] += v*f.y;
        }
    }

    size_t o = (size_t)b*V*CMID + (size_t)r*CMID + f8*8;
    if (CHEB) {
        uint4 u0 = *(const uint4*)(X0h + o);
        const __half2* hp = (const __half2*)&u0;
        #pragma unroll
        for (int j = 0; j < 4; ++j) {
            float2 f = __half22float2(hp[j]);
            acc[2*j]   = 2.f*acc[2*j]   - f.x;
            acc[2*j+1] = 2.f*acc[2*j+1] - f.y;
        }
    }
    __half2 outp[4];
    #pragma unroll
    for (int j = 0; j < 4; ++j) outp[j] = __floats2half2_rn(acc[2*j], acc[2*j+1]);
    *(uint4*)(Yo + o) = *(uint4*)outp;
}

// ---------------- BN apply + ReLU -> fp16 (layer-1 activation) -----------------
__global__ void bnrelu_f16_kernel(const float* __restrict__ Yin,
                                  __half* __restrict__ H,
                                  const float* __restrict__ scale,
                                  const float* __restrict__ shift)
{
    int i4 = blockIdx.x * blockDim.x + threadIdx.x;
    constexpr int TOT4 = M*CMID/4;
    if (i4 >= TOT4) return;
    int c4 = i4 & (CMID/4 - 1);
    float4 v  = ((const float4*)Yin)[i4];
    float4 sc = ((const float4*)scale)[c4];
    float4 sh = ((const float4*)shift)[c4];
    v.x = fmaxf(fmaf(v.x, sc.x, sh.x), 0.f);
    v.y = fmaxf(fmaf(v.y, sc.y, sh.y), 0.f);
    v.z = fmaxf(fmaf(v.z, sc.z, sh.z), 0.f);
    v.w = fmaxf(fmaf(v.w, sc.w, sh.w), 0.f);
    __half2 a = __floats2half2_rn(v.x, v.y);
    __half2 b = __floats2half2_rn(v.z, v.w);
    uint2 o; o.x = *(uint32_t*)&a; o.y = *(uint32_t*)&b;
    ((uint2*)H)[i4] = o;
}

// ---------------- fused BN apply + ReLU (final layer, fp32) --------------------
template<int C>
__global__ void bnrelu_kernel(const float* __restrict__ Yin,
                              float* __restrict__ H,
                              const float* __restrict__ scale,
                              const float* __restrict__ shift)
{
    int i4 = blockIdx.x * blockDim.x + threadIdx.x;
    constexpr int TOT4 = M*C/4;
    if (i4 >= TOT4) return;
    int c4 = i4 % (C/4);
    float4 v  = ((const float4*)Yin)[i4];
    float4 sc = ((const float4*)scale)[c4];
    float4 sh = ((const float4*)shift)[c4];
    v.x = fmaxf(fmaf(v.x, sc.x, sh.x), 0.f);
    v.y = fmaxf(fmaf(v.y, sc.y, sh.y), 0.f);
    v.z = fmaxf(fmaf(v.z, sc.z, sh.z), 0.f);
    v.w = fmaxf(fmaf(v.w, sc.w, sh.w), 0.f);
    ((float4*)H)[i4] = v;
}

// ------------------------------------------------------------------------------
extern "C" void kernel_launch(void* const* d_in, const int* in_sizes, int n_in,
                              void* d_out, int out_size)
{
    const float* x    = (const float*)d_in[0];
    const int*   cols = (const int*)  d_in[2];
    const float* vals = (const float*)d_in[3];
    const float* W1   = (const float*)d_in[4];
    const float* b1   = (const float*)d_in[5];
    const float* g1   = (const float*)d_in[6];
    const float* be1  = (const float*)d_in[7];
    const float* W2   = (const float*)d_in[8];
    const float* b2   = (const float*)d_in[9];
    const float* g2   = (const float*)d_in[10];
    const float* be2  = (const float*)d_in[11];
    const float* W3   = (const float*)d_in[12];
    const float* b3   = (const float*)d_in[13];
    const float* g3   = (const float*)d_in[14];
    const float* be3  = (const float*)d_in[15];
    float* out = (float*)d_out;

    float *y1, *y2, *gsum, *gsq, *gscale, *gshift;
    __half *h1h, *t1h, *t2h;
    unsigned int* ctr;
    cudaGetSymbolAddress((void**)&y1,  g_y1);
    cudaGetSymbolAddress((void**)&y2,  g_y2);
    cudaGetSymbolAddress((void**)&h1h, g_h1h);
    cudaGetSymbolAddress((void**)&t1h, g_t1h);
    cudaGetSymbolAddress((void**)&t2h, g_t2h);
    cudaGetSymbolAddress((void**)&gsum,   g_sum);
    cudaGetSymbolAddress((void**)&gsq,    g_sq);
    cudaGetSymbolAddress((void**)&gscale, g_scale);
    cudaGetSymbolAddress((void**)&gshift, g_shift);
    cudaGetSymbolAddress((void**)&ctr,    g_ctr);

    // smem: NCH*2*W_chunk + 2*A_chunk  (SA=72)
    const int smem1 = 2*2*(64*72*2)  + 2*(128*72*2);    //  73728
    const int smem2 = 3*2*(64*72*2)  + 2*(128*72*2);    //  92160
    const int smem3 = 1*2*(128*72*2) + 2*(128*72*2);    //  73728
    cudaFuncSetAttribute(gemm_mma<128, 64, 1, false, false>, cudaFuncAttributeMaxDynamicSharedMemorySize, smem1);
    cudaFuncSetAttribute(gemm_mma< 64, 64, 3, false, true >, cudaFuncAttributeMaxDynamicSharedMemorySize, smem2);
    cudaFuncSetAttribute(gemm_mma< 64,128, 1, true , false>, cudaFuncAttributeMaxDynamicSharedMemorySize, smem3);

    const int GEMM_GRID   = M / 128;           // 768
    const int SPMM_GRID   = V/2 * 32 / 256;    // 3072
    const int F16_GRID    = M*CMID/4/256;      // 6144
    const int BNR_GRID128 = M*CIN/4/256;       // 12288

    // ---- layer 1: y1 = x @ W1 + b1 ; fused stats+finalize ----
    gemm_mma<128, 64, 1, false, false><<<GEMM_GRID, 256, smem1>>>(
        x, nullptr, nullptr, W1, b1, nullptr, nullptr, y1,
        g1, be1, gsum + 0, gsq + 0, gscale + 0, gshift + 0, ctr + 0);

    // ---- h1 = bnrelu(y1) in fp16 ----
    bnrelu_f16_kernel<<<F16_GRID, 256>>>(y1, h1h, gscale + 0, gshift + 0);

    // ---- layer 2: Chebyshev K=3 in fp16 ----
    spmm_f16<false><<<SPMM_GRID, 256>>>(cols, vals, h1h, nullptr, t1h);   // t1 = S h1
    spmm_f16<true ><<<SPMM_GRID, 256>>>(cols, vals, t1h, h1h, t2h);       // t2 = 2 S t1 - h1
    gemm_mma<64, 64, 3, false, true><<<GEMM_GRID, 256, smem2>>>(
        h1h, t1h, t2h, W2, b2, nullptr, nullptr, y2,
        g2, be2, gsum + 128, gsq + 128, gscale + 128, gshift + 128, ctr + 1);

    // ---- layer 3: out = bnrelu( bnrelu(y2) @ W3 + b3 ) ----
    gemm_mma<64, 128, 1, true, false><<<GEMM_GRID, 256, smem3>>>(
        y2, nullptr, nullptr, W3, b3, gscale + 128, gshift + 128, out,
        g3, be3, gsum + 256, gsq + 256, gscale + 256, gshift + 256, ctr + 2);
    bnrelu_kernel<CIN><<<BNR_GRID128, 256>>>(out, out, gscale + 256, gshift + 256);
}

// round 10
// speedup vs baseline: 1.4881x; 1.0595x over previous
#include <cuda_runtime.h>
#include <cuda_fp16.h>
#include <math.h>
#include <stdint.h>

#define V     49152
#define BATCH 2
#define M     (BATCH*V)      // 98304
#define DEG   20
#define CIN   128
#define CMID  64

// ---------------- scratch (device globals; zero-initialized) ------------------
__device__ __align__(128) float  g_y1[M*CMID];
__device__ __align__(128) float  g_y2[M*CMID];
__device__ __align__(128) __half g_h1h[M*CMID];
__device__ __align__(128) __half g_t1h[M*CMID];
__device__ __align__(128) __half g_t2h[M*CMID];
__device__ __align__(128) float g_sum[3*128];
__device__ __align__(128) float g_sq [3*128];
__device__ __align__(128) float g_scale[3*128];
__device__ __align__(128) float g_shift[3*128];
__device__ unsigned int g_ctr[3];

// ---------------- PTX helpers --------------------------------------------------
__device__ __forceinline__ void mma_h(float* c, const uint32_t* a, const uint32_t* b) {
    asm volatile(
        "mma.sync.aligned.m16n8k16.row.col.f32.f16.f16.f32 "
        "{%0,%1,%2,%3}, {%4,%5,%6,%7}, {%8,%9}, {%0,%1,%2,%3};"
        : "+f"(c[0]), "+f"(c[1]), "+f"(c[2]), "+f"(c[3])
        : "r"(a[0]), "r"(a[1]), "r"(a[2]), "r"(a[3]), "r"(b[0]), "r"(b[1]));
}
__device__ __forceinline__ void ldsm_x4(uint32_t* r, uint32_t addr) {
    asm volatile("ldmatrix.sync.aligned.m8n8.x4.shared.b16 {%0,%1,%2,%3}, [%4];"
        : "=r"(r[0]), "=r"(r[1]), "=r"(r[2]), "=r"(r[3]) : "r"(addr));
}
__device__ __forceinline__ void ldsm_x2(uint32_t* r, uint32_t addr) {
    asm volatile("ldmatrix.sync.aligned.m8n8.x2.shared.b16 {%0,%1}, [%2];"
        : "=r"(r[0]), "=r"(r[1]) : "r"(addr));
}
__device__ __forceinline__ uint32_t smem_u32(const void* p) {
    uint32_t a;
    asm("{ .reg .u64 t; cvta.to.shared.u64 t, %1; cvt.u32.u64 %0, t; }" : "=r"(a) : "l"(p));
    return a;
}
// fp16 hi/lo split of a float pair (hi + lo reproduces ~22 mantissa bits)
__device__ __forceinline__ void split2h(float a, float b, uint32_t& hi, uint32_t& lo) {
    __half2 h = __floats2half2_rn(a, b);
    float2 f = __half22float2(h);
    __half2 l = __floats2half2_rn(a - f.x, b - f.y);
    hi = *reinterpret_cast<uint32_t*>(&h);
    lo = *reinterpret_cast<uint32_t*>(&l);
}

// ---------------- tensor-core GEMM (HMMA fp16, chunked, ldmatrix) --------------
// Y[128-row tile, NOUT] = sum_s A_s[tile, K] @ W[s*K.., NOUT] + bias
// MODE 0: fp32 sources, fp16 hi/lo split of A and W, 3 MMA passes.
// MODE 1: exact-fp16 sources (A used directly), W fp16 hi/lo, 2 MMA passes.
// BN0 (MODE 0 only): fused BN+ReLU on source 0 while staging.
// Fused BN-stats epilogue; last block computes this layer's scale/shift and
// resets the accumulators (replay-safe).
template<int K, int NOUT, int NSRC, bool BN0, int MODE>
__global__ void __launch_bounds__(256) gemm_mma(
    const void* __restrict__ A0v, const void* __restrict__ A1v, const void* __restrict__ A2v,
    const float* __restrict__ W, const float* __restrict__ bias,
    const float* __restrict__ bsc, const float* __restrict__ bsh,
    float* __restrict__ Y,
    const float* __restrict__ gamma, const float* __restrict__ beta,
    float* __restrict__ gs, float* __restrict__ gq,
    float* __restrict__ oscale, float* __restrict__ oshift,
    unsigned int* __restrict__ ctr)
{
    constexpr int KT   = NSRC*K;
    constexpr int NCH  = KT/64;               // 64-col chunks
    constexpr int SA   = 72;                  // padded row stride (fp16 elems)
    constexpr int WCH  = NOUT*SA*2;           // bytes per W chunk (hi or lo)
    constexpr int ACH  = 128*SA*2;            // bytes per A buffer
    constexpr int OFF_A = NCH*2*WCH;

    extern __shared__ char smc[];
    const uint32_t sbase = smem_u32(smc);

    const int t    = threadIdx.x;
    const int wid  = t >> 5, lane = t & 31;
    const int row0 = blockIdx.x * 128;
    const int g    = lane >> 2, tg = lane & 3;
    const int rb   = wid*16;

    // ---- stage W: Wt[n][k] = W[kt][n] per chunk, fp16 hi/lo ----
    for (int i = t; i < KT*NOUT; i += 256) {
        int n = i % NOUT, kt = i / NOUT;
        int c = kt >> 6, kk = kt & 63;
        float w = W[i];
        __half h = __float2half_rn(w);
        *(__half*)(smc + c*2*WCH + (n*SA + kk)*2)       = h;
        *(__half*)(smc + c*2*WCH + WCH + (n*SA + kk)*2) = __float2half_rn(w - __half2float(h));
    }

    constexpr int NB = NOUT/8;
    float acc[NB][4];
    #pragma unroll
    for (int nb = 0; nb < NB; ++nb)
        acc[nb][0] = acc[nb][1] = acc[nb][2] = acc[nb][3] = 0.f;

    const uint32_t aHi  = sbase + OFF_A + ((rb + (lane & 15))*SA + (lane >> 4)*8)*2;
    const uint32_t wlan = (((lane & 7)*SA + ((lane >> 3) & 1)*8))*2;

    #pragma unroll
    for (int c = 0; c < NCH; ++c) {
        const int s  = (c*64) / K;
        const int ko = (c*64) % K;
        const void* Av = (s == 0) ? A0v : ((s == 1) ? A1v : A2v);

        __syncthreads();   // W staged (c==0) / previous chunk consumed
        if (MODE == 1) {
            // exact fp16 source: raw 16-byte copies, no conversion
            const __half* A = (const __half*)Av;
            for (int i = t; i < 128*8; i += 256) {
                int r = i >> 3, c8 = i & 7;
                uint4 u = *(const uint4*)(A + (size_t)(row0 + r)*K + ko + c8*8);
                *(uint4*)(smc + OFF_A + (r*SA + c8*8)*2) = u;
            }
        } else {
            const float* A = (const float*)Av;
            for (int i = t; i < 128*16; i += 256) {
                int r = i >> 4, c4 = i & 15;
                float4 v = *(const float4*)(A + (size_t)(row0 + r)*K + ko + c4*4);
                if (BN0 && s == 0) {
                    float4 sc = *(const float4*)(bsc + ko + c4*4);
                    float4 sh = *(const float4*)(bsh + ko + c4*4);
                    v.x = fmaxf(fmaf(v.x, sc.x, sh.x), 0.f);
                    v.y = fmaxf(fmaf(v.y, sc.y, sh.y), 0.f);
                    v.z = fmaxf(fmaf(v.z, sc.z, sh.z), 0.f);
                    v.w = fmaxf(fmaf(v.w, sc.w, sh.w), 0.f);
                }
                uint32_t* dh = (uint32_t*)(smc + OFF_A + (r*SA + c4*4)*2);
                uint32_t* dl = (uint32_t*)(smc + OFF_A + ACH + (r*SA + c4*4)*2);
                split2h(v.x, v.y, dh[0], dl[0]);
                split2h(v.z, v.w, dh[1], dl[1]);
            }
        }
        __syncthreads();

        const uint32_t wch = sbase + c*2*WCH + wlan;
        #pragma unroll
        for (int kk = 0; kk < 4; ++kk) {
            uint32_t ah[4];
            ldsm_x4(ah, aHi + kk*32);
            if (MODE == 1) {
                #pragma unroll
                for (int nb = 0; nb < NB; ++nb) {
                    uint32_t bh[2], bl[2];
                    uint32_t wa = wch + nb*8*SA*2 + kk*32;
                    ldsm_x2(bh, wa);
                    ldsm_x2(bl, wa + WCH);
                    mma_h(acc[nb], ah, bh);   // A*Whi
                    mma_h(acc[nb], ah, bl);   // A*Wlo
                }
            } else {
                uint32_t al[4];
                ldsm_x4(al, aHi + ACH + kk*32);
                #pragma unroll
                for (int nb = 0; nb < NB; ++nb) {
                    uint32_t bh[2], bl[2];
                    uint32_t wa = wch + nb*8*SA*2 + kk*32;
                    ldsm_x2(bh, wa);
                    ldsm_x2(bl, wa + WCH);
                    mma_h(acc[nb], ah, bh);   // hi*hi
                    mma_h(acc[nb], ah, bl);   // hi*lo
                    mma_h(acc[nb], al, bh);   // lo*hi
                }
            }
        }
    }

    __syncthreads();   // compute done -> smem reusable for stats reduction
    float* redS = (float*)smc;               // [8][NOUT]
    float* redQ = (float*)smc + 8*NOUT;      // [8][NOUT]

    // ---- store + per-warp column partials ----
    {
        float* y0 = Y + (size_t)(row0 + rb + g)*NOUT;
        float* y8 = Y + (size_t)(row0 + rb + g + 8)*NOUT;
        #pragma unroll
        for (int nb = 0; nb < NB; ++nb) {
            int c = nb*8 + tg*2;
            float2 bb = __ldg((const float2*)(bias + c));
            float y00 = acc[nb][0] + bb.x, y01 = acc[nb][1] + bb.y;
            float y80 = acc[nb][2] + bb.x, y81 = acc[nb][3] + bb.y;
            *(float2*)(y0 + c) = make_float2(y00, y01);
            *(float2*)(y8 + c) = make_float2(y80, y81);
            float s0 = y00 + y80, q0 = y00*y00 + y80*y80;
            float s1 = y01 + y81, q1 = y01*y01 + y81*y81;
            #pragma unroll
            for (int off = 4; off <= 16; off <<= 1) {
                s0 += __shfl_xor_sync(0xffffffffu, s0, off);
                q0 += __shfl_xor_sync(0xffffffffu, q0, off);
                s1 += __shfl_xor_sync(0xffffffffu, s1, off);
                q1 += __shfl_xor_sync(0xffffffffu, q1, off);
            }
            if (lane < 4) {
                redS[wid*NOUT + c]     = s0;
                redS[wid*NOUT + c + 1] = s1;
                redQ[wid*NOUT + c]     = q0;
                redQ[wid*NOUT + c + 1] = q1;
            }
        }
    }
    __syncthreads();

    if (t < NOUT) {
        float s = 0.f, q = 0.f;
        #pragma unroll
        for (int w = 0; w < 8; ++w) { s += redS[w*NOUT + t]; q += redQ[w*NOUT + t]; }
        atomicAdd(&gs[t], s);
        atomicAdd(&gq[t], q);
    }
    __threadfence();
    __syncthreads();

    __shared__ bool s_last;
    if (t == 0) s_last = (atomicAdd(ctr, 1u) == (unsigned)gridDim.x - 1u);
    __syncthreads();
    if (s_last) {
        if (t < NOUT) {
            float mean = gs[t] * (1.f/(float)M);
            float var  = gq[t] * (1.f/(float)M) - mean*mean;
            float sc   = gamma[t] * rsqrtf(var + 1e-5f);
            oscale[t] = sc;
            oshift[t] = beta[t] - mean*sc;
            gs[t] = 0.f; gq[t] = 0.f;      // replay-safe reset
        }
        if (t == 0) *ctr = 0u;
    }
}

// ---------------- SpMM fp16: 2 rows/warp, 8 fp16 channels/lane -----------------
template<bool CHEB>
__global__ void spmm_f16(const int*   __restrict__ cols,
                         const float* __restrict__ vals,
                         const __half* __restrict__ X,
                         const __half* __restrict__ X0h,
                         __half* __restrict__ Yo)
{
    int warp = (blockIdx.x * blockDim.x + threadIdx.x) >> 5;
    int lane = threadIdx.x & 31;
    int r = warp*2 + (lane >> 4);
    if (r >= V) return;
    const int b  = (lane >> 3) & 1;
    const int f8 = lane & 7;
    const __half* Xb = X + (size_t)b*V*CMID + f8*8;

    float acc[8];
    #pragma unroll
    for (int j = 0; j < 8; ++j) acc[j] = 0.f;

    {
        int c = __ldg(&cols[r]); float v = __ldg(&vals[r]);
        uint4 u = *(const uint4*)(Xb + (size_t)c*CMID);
        const __half2* hp = (const __half2*)&u;
        #pragma unroll
        for (int j = 0; j < 4; ++j) {
            float2 f = __half22float2(hp[j]);
            acc[2*j]   += v*f.x;
            acc[2*j+1] += v*f.y;
        }
    }
    const int base = V + r*DEG;
    #pragma unroll
    for (int d = 0; d < DEG; ++d) {
        int c = __ldg(&cols[base+d]); float v = __ldg(&vals[base+d]);
        uint4 u = *(const uint4*)(Xb + (size_t)c*CMID);
        const __half2* hp = (const __half2*)&u;
        #pragma unroll
        for (int j = 0; j < 4; ++j) {
            float2 f = __half22float2(hp[j]);
            acc[2*j]   += v*f.x;
            acc[2*j+1] += v*f.y;
        }
    }

    size_t o = (size_t)b*V*CMID + (size_t)r*CMID + f8*8;
    if (CHEB) {
        uint4 u0 = *(const uint4*)(X0h + o);
        const __half2* hp = (const __half2*)&u0;
        #pragma unroll
        for (int j = 0; j < 4; ++j) {
            float2 f = __half22float2(hp[j]);
            acc[2*j]   = 2.f*acc[2*j]   - f.x;
            acc[2*j+1] = 2.f*acc[2*j+1] - f.y;
        }
    }
    __half2 outp[4];
    #pragma unroll
    for (int j = 0; j < 4; ++j) outp[j] = __floats2half2_rn(acc[2*j], acc[2*j+1]);
    *(uint4*)(Yo + o) = *(uint4*)outp;
}

// ---------------- BN apply + ReLU -> fp16 (layer-1 activation) -----------------
__global__ void bnrelu_f16_kernel(const float* __restrict__ Yin,
                                  __half* __restrict__ H,
                                  const float* __restrict__ scale,
                                  const float* __restrict__ shift)
{
    int i4 = blockIdx.x * blockDim.x + threadIdx.x;
    constexpr int TOT4 = M*CMID/4;
    if (i4 >= TOT4) return;
    int c4 = i4 & (CMID/4 - 1);
    float4 v  = ((const float4*)Yin)[i4];
    float4 sc = ((const float4*)scale)[c4];
    float4 sh = ((const float4*)shift)[c4];
    v.x = fmaxf(fmaf(v.x, sc.x, sh.x), 0.f);
    v.y = fmaxf(fmaf(v.y, sc.y, sh.y), 0.f);
    v.z = fmaxf(fmaf(v.z, sc.z, sh.z), 0.f);
    v.w = fmaxf(fmaf(v.w, sc.w, sh.w), 0.f);
    __half2 a = __floats2half2_rn(v.x, v.y);
    __half2 b = __floats2half2_rn(v.z, v.w);
    uint2 o; o.x = *(uint32_t*)&a; o.y = *(uint32_t*)&b;
    ((uint2*)H)[i4] = o;
}

// ---------------- fused BN apply + ReLU (final layer, fp32) --------------------
template<int C>
__global__ void bnrelu_kernel(const float* __restrict__ Yin,
                              float* __restrict__ H,
                              const float* __restrict__ scale,
                              const float* __restrict__ shift)
{
    int i4 = blockIdx.x * blockDim.x + threadIdx.x;
    constexpr int TOT4 = M*C/4;
    if (i4 >= TOT4) return;
    int c4 = i4 % (C/4);
    float4 v  = ((const float4*)Yin)[i4];
    float4 sc = ((const float4*)scale)[c4];
    float4 sh = ((const float4*)shift)[c4];
    v.x = fmaxf(fmaf(v.x, sc.x, sh.x), 0.f);
    v.y = fmaxf(fmaf(v.y, sc.y, sh.y), 0.f);
    v.z = fmaxf(fmaf(v.z, sc.z, sh.z), 0.f);
    v.w = fmaxf(fmaf(v.w, sc.w, sh.w), 0.f);
    ((float4*)H)[i4] = v;
}

// ------------------------------------------------------------------------------
extern "C" void kernel_launch(void* const* d_in, const int* in_sizes, int n_in,
                              void* d_out, int out_size)
{
    const float* x    = (const float*)d_in[0];
    const int*   cols = (const int*)  d_in[2];
    const float* vals = (const float*)d_in[3];
    const float* W1   = (const float*)d_in[4];
    const float* b1   = (const float*)d_in[5];
    const float* g1   = (const float*)d_in[6];
    const float* be1  = (const float*)d_in[7];
    const float* W2   = (const float*)d_in[8];
    const float* b2   = (const float*)d_in[9];
    const float* g2   = (const float*)d_in[10];
    const float* be2  = (const float*)d_in[11];
    const float* W3   = (const float*)d_in[12];
    const float* b3   = (const float*)d_in[13];
    const float* g3   = (const float*)d_in[14];
    const float* be3  = (const float*)d_in[15];
    float* out = (float*)d_out;

    float *y1, *y2, *gsum, *gsq, *gscale, *gshift;
    __half *h1h, *t1h, *t2h;
    unsigned int* ctr;
    cudaGetSymbolAddress((void**)&y1,  g_y1);
    cudaGetSymbolAddress((void**)&y2,  g_y2);
    cudaGetSymbolAddress((void**)&h1h, g_h1h);
    cudaGetSymbolAddress((void**)&t1h, g_t1h);
    cudaGetSymbolAddress((void**)&t2h, g_t2h);
    cudaGetSymbolAddress((void**)&gsum,   g_sum);
    cudaGetSymbolAddress((void**)&gsq,    g_sq);
    cudaGetSymbolAddress((void**)&gscale, g_scale);
    cudaGetSymbolAddress((void**)&gshift, g_shift);
    cudaGetSymbolAddress((void**)&ctr,    g_ctr);

    // smem (SA=72): all three = 73728 B -> 3 CTAs/SM
    const int smem1 = 2*2*(64*72*2)  + 2*(128*72*2);    // 73728
    const int smem2 = 3*2*(64*72*2)  + 1*(128*72*2);    // 73728
    const int smem3 = 1*2*(128*72*2) + 2*(128*72*2);    // 73728
    cudaFuncSetAttribute(gemm_mma<128, 64, 1, false, 0>, cudaFuncAttributeMaxDynamicSharedMemorySize, smem1);
    cudaFuncSetAttribute(gemm_mma< 64, 64, 3, false, 1>, cudaFuncAttributeMaxDynamicSharedMemorySize, smem2);
    cudaFuncSetAttribute(gemm_mma< 64,128, 1, true , 0>, cudaFuncAttributeMaxDynamicSharedMemorySize, smem3);

    const int GEMM_GRID   = M / 128;           // 768
    const int SPMM_GRID   = V/2 * 32 / 256;    // 3072
    const int F16_GRID    = M*CMID/4/256;      // 6144
    const int BNR_GRID128 = M*CIN/4/256;       // 12288

    // ---- layer 1: y1 = x @ W1 + b1 ; fused stats+finalize ----
    gemm_mma<128, 64, 1, false, 0><<<GEMM_GRID, 256, smem1>>>(
        x, nullptr, nullptr, W1, b1, nullptr, nullptr, y1,
        g1, be1, gsum + 0, gsq + 0, gscale + 0, gshift + 0, ctr + 0);

    // ---- h1 = bnrelu(y1) in fp16 ----
    bnrelu_f16_kernel<<<F16_GRID, 256>>>(y1, h1h, gscale + 0, gshift + 0);

    // ---- layer 2: Chebyshev K=3 in fp16 (exact-A 2-pass GEMM) ----
    spmm_f16<false><<<SPMM_GRID, 256>>>(cols, vals, h1h, nullptr, t1h);   // t1 = S h1
    spmm_f16<true ><<<SPMM_GRID, 256>>>(cols, vals, t1h, h1h, t2h);       // t2 = 2 S t1 - h1
    gemm_mma<64, 64, 3, false, 1><<<GEMM_GRID, 256, smem2>>>(
        h1h, t1h, t2h, W2, b2, nullptr, nullptr, y2,
        g2, be2, gsum + 128, gsq + 128, gscale + 128, gshift + 128, ctr + 1);

    // ---- layer 3: out = bnrelu( bnrelu(y2) @ W3 + b3 ) ----
    gemm_mma<64, 128, 1, true, 0><<<GEMM_GRID, 256, smem3>>>(
        y2, nullptr, nullptr, W3, b3, gscale + 128, gshift + 128, out,
        g3, be3, gsum + 256, gsq + 256, gscale + 256, gshift + 256, ctr + 2);
    bnrelu_kernel<CIN><<<BNR_GRID128, 256>>>(out, out, gscale + 256, gshift + 256);
}